// round 15
// baseline (speedup 1.0000x reference)
#include <cuda_runtime.h>
#include <mma.h>
#include <cstdint>

using namespace nvcuda;

#define NT  8192
#define DIM 512
#define HID 2048
#define NE  4
#define BM  128
#define BN  128
#define BK  16
#define APITCH 20
#define BPITCH 132

// ---------------- device scratch (no allocs allowed) ----------------
__device__ __align__(16) int   g_cnt[NE];
__device__ __align__(16) int   g_tok[NE * NT];
__device__ __align__(16) int   g_slot[NT * 2];
__device__ __align__(16) float g_gval[NT * 2];
__device__ __align__(16) float g_hr [(size_t)NT * DIM];        // tf32-rounded h
__device__ __align__(16) float g_w1r[(size_t)NE * DIM * HID];  // tf32-rounded w1
__device__ __align__(16) float g_w2r[(size_t)NE * HID * DIM];  // tf32-rounded w2
__device__ __align__(16) float g_mid[(size_t)NE * NT * HID];   // tf32-rounded mid
__device__ __align__(16) float g_y  [(size_t)NE * NT * DIM];

// ---------------- reset ----------------
__global__ void reset_kernel() {
    if (threadIdx.x < NE) g_cnt[threadIdx.x] = 0;
}

// ---------------- gating (proven) ----------------
__global__ void gate_kernel(const float* __restrict__ h,
                            const float* __restrict__ wg) {
    int gw   = (blockIdx.x * blockDim.x + threadIdx.x) >> 5;
    int lane = threadIdx.x & 31;
    if (gw >= NT) return;
    const float* hr = h + (size_t)gw * DIM;
    float a0 = 0.f, a1 = 0.f, a2 = 0.f, a3 = 0.f;
    for (int i = lane; i < DIM; i += 32) {
        float  hv = hr[i];
        float4 w  = reinterpret_cast<const float4*>(wg)[i];
        a0 += hv * w.x; a1 += hv * w.y; a2 += hv * w.z; a3 += hv * w.w;
    }
    #pragma unroll
    for (int o = 16; o; o >>= 1) {
        a0 += __shfl_xor_sync(0xffffffffu, a0, o);
        a1 += __shfl_xor_sync(0xffffffffu, a1, o);
        a2 += __shfl_xor_sync(0xffffffffu, a2, o);
        a3 += __shfl_xor_sync(0xffffffffu, a3, o);
    }
    if (lane == 0) {
        float l[4] = {a0, a1, a2, a3};
        int i0 = 0;
        #pragma unroll
        for (int e = 1; e < 4; e++) if (l[e] > l[i0]) i0 = e;
        int i1 = -1;
        #pragma unroll
        for (int e = 0; e < 4; e++)
            if (e != i0 && (i1 < 0 || l[e] > l[i1])) i1 = e;
        float p1  = expf(l[i1] - l[i0]);
        float inv = 1.0f / (1.0f + p1);
        int p = atomicAdd(&g_cnt[i0], 1);
        g_tok[i0 * NT + p] = gw;
        g_slot[gw * 2]     = i0 * NT + p;
        g_gval[gw * 2]     = inv;
        int q = atomicAdd(&g_cnt[i1], 1);
        g_tok[i1 * NT + q] = gw;
        g_slot[gw * 2 + 1] = i1 * NT + q;
        g_gval[gw * 2 + 1] = p1 * inv;
    }
}

// ---------------- tf32 rounding pre-pass (once per tensor) ----------------
__global__ void round_tf32_kernel(const float* __restrict__ src,
                                  float* __restrict__ dst, int n4) {
    int i = blockIdx.x * blockDim.x + threadIdx.x;
    if (i >= n4) return;
    float4 v = reinterpret_cast<const float4*>(src)[i];
    v.x = wmma::__float_to_tf32(v.x);
    v.y = wmma::__float_to_tf32(v.y);
    v.z = wmma::__float_to_tf32(v.z);
    v.w = wmma::__float_to_tf32(v.w);
    reinterpret_cast<float4*>(dst)[i] = v;
}

// ---------------- wmma tf32 grouped GEMM, 1 term, double-buffered ----------------
// D[128,128] = A[128,K] @ B[K,128]; A rows gathered (GEMM1) or direct (GEMM2).
// Operands pre-rounded to tf32 in gmem. 8 warps: 4(M) x 2(N), warp tile 32x64.
// NO min-blocks launch bound: let regs float (~160) to avoid accumulator spills.
template<int KTOT, int NTOT, bool GATHER, bool ROUND_OUT>
__global__ void __launch_bounds__(256) gemm_kernel(const float* __restrict__ Ain,
                                                   const float* __restrict__ Bg,
                                                   const float* __restrict__ bias) {
    const int e   = blockIdx.z;
    const int cnt = g_cnt[e];
    const int m0  = blockIdx.y * BM;
    if (m0 >= cnt) return;
    const int n0  = blockIdx.x * BN;

    const float* Ag = GATHER ? Ain : g_mid;
    float* outp     = ROUND_OUT ? g_mid : g_y;

    __shared__ float As[2][BM][APITCH];   // 20.0 KB
    __shared__ float Bs[2][BK][BPITCH];   // 16.5 KB
    __shared__ float Epi[8][256];         //  8.0 KB  (total 44.5 KB)

    const int tid  = threadIdx.x;
    const int wid  = tid >> 5;
    const int lane = tid & 31;

    // A loader (R7 map): row lr = tid>>1, 8 k's at lk
    const int lr = tid >> 1, lk = (tid & 1) * 8;
    int arow = m0 + lr; if (arow >= cnt) arow = cnt - 1;
    const float* aptr;
    if (GATHER) aptr = Ag + (size_t)g_tok[e * NT + arow] * KTOT + lk;
    else        aptr = Ag + ((size_t)e * NT + arow) * KTOT + lk;

    // B loader: k-row kb = tid>>4, 8 cols at bc
    const int kb = tid >> 4, bc = (tid & 15) * 8;
    const float* bptr = Bg + (size_t)e * KTOT * NTOT + (size_t)kb * NTOT + n0 + bc;

    // warp tiling
    const int mstrip = (wid >> 1) * 32;
    const int nstrip = (wid & 1) * 64;

    wmma::fragment<wmma::accumulator, 16, 16, 8, float> acc[2][4];
    #pragma unroll
    for (int i = 0; i < 2; i++)
        #pragma unroll
        for (int j = 0; j < 4; j++) wmma::fill_fragment(acc[i][j], 0.0f);

    const int KT = KTOT / BK;
    float4 pa0, pa1, pb0, pb1;

    // prologue: tile 0 -> regs -> stage 0; tile 1 -> regs
    pa0 = *reinterpret_cast<const float4*>(aptr);
    pa1 = *reinterpret_cast<const float4*>(aptr + 4);
    pb0 = *reinterpret_cast<const float4*>(bptr);
    pb1 = *reinterpret_cast<const float4*>(bptr + 4);
    *reinterpret_cast<float4*>(&As[0][lr][lk])     = pa0;
    *reinterpret_cast<float4*>(&As[0][lr][lk + 4]) = pa1;
    *reinterpret_cast<float4*>(&Bs[0][kb][bc])     = pb0;
    *reinterpret_cast<float4*>(&Bs[0][kb][bc + 4]) = pb1;
    if (KT > 1) {
        pa0 = *reinterpret_cast<const float4*>(aptr + BK);
        pa1 = *reinterpret_cast<const float4*>(aptr + BK + 4);
        pb0 = *reinterpret_cast<const float4*>(bptr + (size_t)BK * NTOT);
        pb1 = *reinterpret_cast<const float4*>(bptr + (size_t)BK * NTOT + 4);
    }
    __syncthreads();

    for (int kt = 0; kt < KT; kt++) {
        const int s = kt & 1;

        // store tile kt+1 (regs) -> stage s^1 (its readers finished at the last barrier)
        if (kt + 1 < KT) {
            *reinterpret_cast<float4*>(&As[s ^ 1][lr][lk])     = pa0;
            *reinterpret_cast<float4*>(&As[s ^ 1][lr][lk + 4]) = pa1;
            *reinterpret_cast<float4*>(&Bs[s ^ 1][kb][bc])     = pb0;
            *reinterpret_cast<float4*>(&Bs[s ^ 1][kb][bc + 4]) = pb1;
        }
        // issue LDG for tile kt+2
        if (kt + 2 < KT) {
            const float* ap = aptr + (kt + 2) * BK;
            const float* bp = bptr + (size_t)(kt + 2) * BK * NTOT;
            pa0 = *reinterpret_cast<const float4*>(ap);
            pa1 = *reinterpret_cast<const float4*>(ap + 4);
            pb0 = *reinterpret_cast<const float4*>(bp);
            pb1 = *reinterpret_cast<const float4*>(bp + 4);
        }

        // compute stage s: 2 k8 steps, 1 term
        #pragma unroll
        for (int ks = 0; ks < 2; ks++) {
            wmma::fragment<wmma::matrix_a, 16, 16, 8, wmma::precision::tf32, wmma::row_major> af[2];
            #pragma unroll
            for (int i = 0; i < 2; i++)
                wmma::load_matrix_sync(af[i], &As[s][mstrip + 16 * i][ks * 8], APITCH);
            wmma::fragment<wmma::matrix_b, 16, 16, 8, wmma::precision::tf32, wmma::row_major> bf[4];
            #pragma unroll
            for (int j = 0; j < 4; j++)
                wmma::load_matrix_sync(bf[j], &Bs[s][ks * 8][nstrip + 16 * j], BPITCH);
            #pragma unroll
            for (int i = 0; i < 2; i++)
                #pragma unroll
                for (int j = 0; j < 4; j++)
                    wmma::mma_sync(acc[i][j], af[i], bf[j], acc[i][j]);
        }
        __syncthreads();
    }

    // ---- epilogue (proven staging): bias (+relu+round), float4 stores ----
    float* epi = &Epi[wid][0];
    const int rr = lane >> 1;
    const int cc = (lane & 1) * 8;
    #pragma unroll
    for (int i = 0; i < 2; i++) {
        #pragma unroll
        for (int j = 0; j < 4; j++) {
            wmma::store_matrix_sync(epi, acc[i][j], 16, wmma::mem_row_major);
            __syncwarp();
            const int r     = m0 + mstrip + 16 * i + rr;
            const int cbase = n0 + nstrip + 16 * j + cc;
            if (r < cnt) {
                float v[8];
                #pragma unroll
                for (int t = 0; t < 8; t++) {
                    v[t] = epi[rr * 16 + cc + t] + bias[(size_t)e * NTOT + cbase + t];
                    if (ROUND_OUT) v[t] = wmma::__float_to_tf32(fmaxf(v[t], 0.f));
                }
                float* orow = outp + ((size_t)e * NT + r) * NTOT + cbase;
                *reinterpret_cast<float4*>(orow)     = make_float4(v[0], v[1], v[2], v[3]);
                *reinterpret_cast<float4*>(orow + 4) = make_float4(v[4], v[5], v[6], v[7]);
            }
            __syncwarp();
        }
    }
}

// ---------------- combine (proven) ----------------
__global__ void combine_kernel(float* __restrict__ out) {
    int idx = blockIdx.x * blockDim.x + threadIdx.x;
    if (idx >= NT * (DIM / 4)) return;
    int n = idx / (DIM / 4);
    int c = idx % (DIM / 4);
    int   sA = g_slot[n * 2],     sB = g_slot[n * 2 + 1];
    float gA = g_gval[n * 2],     gB = g_gval[n * 2 + 1];
    const float4* y4 = reinterpret_cast<const float4*>(g_y);
    float4 a = y4[(size_t)sA * (DIM / 4) + c];
    float4 b = y4[(size_t)sB * (DIM / 4) + c];
    float4 o;
    o.x = gA * a.x + gB * b.x;
    o.y = gA * a.y + gB * b.y;
    o.z = gA * a.z + gB * b.z;
    o.w = gA * a.w + gB * b.w;
    reinterpret_cast<float4*>(out)[idx] = o;
}

// ---------------- launch ----------------
extern "C" void kernel_launch(void* const* d_in, const int* in_sizes, int n_in,
                              void* d_out, int out_size) {
    const float* h  = (const float*)d_in[0];   // [NT, DIM]
    const float* wg = (const float*)d_in[1];   // [DIM, NE]
    const float* w1 = (const float*)d_in[2];   // [NE, DIM, HID] = [e][k][n]
    const float* b1 = (const float*)d_in[3];   // [NE, HID]
    const float* w2 = (const float*)d_in[4];   // [NE, HID, DIM] = [e][k][n]
    const float* b2 = (const float*)d_in[5];   // [NE, DIM]
    float* out = (float*)d_out;                // [NT, DIM]

    reset_kernel<<<1, 32>>>();
    gate_kernel<<<(NT * 32) / 256, 256>>>(h, wg);
    round_tf32_kernel<<<(NT * DIM / 4 + 255) / 256, 256>>>(h, g_hr, NT * DIM / 4);
    round_tf32_kernel<<<(NE * DIM * HID / 4 + 255) / 256, 256>>>(w1, g_w1r, NE * DIM * HID / 4);
    round_tf32_kernel<<<(NE * HID * DIM / 4 + 255) / 256, 256>>>(w2, g_w2r, NE * HID * DIM / 4);
    {   // GEMM1: mid = round_tf32(relu(h_r[tok] @ w1_r[e] + b1))
        dim3 g(HID / BN, NT / BM, NE);
        gemm_kernel<DIM, HID, true, true><<<g, 256>>>(g_hr, g_w1r, b1);
    }
    {   // GEMM2: y = mid @ w2_r[e] + b2
        dim3 g(DIM / BN, NT / BM, NE);
        gemm_kernel<HID, DIM, false, false><<<g, 256>>>(g_hr /*unused*/, g_w2r, b2);
    }
    combine_kernel<<<(NT * (DIM / 4) + 255) / 256, 256>>>(out);
}

// round 17
// speedup vs baseline: 6.6856x; 6.6856x over previous
#include <cuda_runtime.h>
#include <mma.h>
#include <cstdint>

using namespace nvcuda;

#define NT  8192
#define DIM 512
#define HID 2048
#define NE  4
#define BM  64
#define BN  64
#define BK  32
#define APITCH 36
#define BPITCH 68

// ---------------- device scratch (no allocs allowed) ----------------
__device__ __align__(16) int   g_cnt[NE];
__device__ __align__(16) int   g_tok[NE * NT];
__device__ __align__(16) int   g_slot[NT * 2];
__device__ __align__(16) float g_gval[NT * 2];
__device__ __align__(16) float g_mid[(size_t)NE * NT * HID];   // tf32-rounded mid
__device__ __align__(16) float g_y  [(size_t)NE * NT * DIM];

// ---------------- reset ----------------
__global__ void reset_kernel() {
    if (threadIdx.x < NE) g_cnt[threadIdx.x] = 0;
}

// ---------------- gating (proven) ----------------
__global__ void gate_kernel(const float* __restrict__ h,
                            const float* __restrict__ wg) {
    int gw   = (blockIdx.x * blockDim.x + threadIdx.x) >> 5;
    int lane = threadIdx.x & 31;
    if (gw >= NT) return;
    const float* hr = h + (size_t)gw * DIM;
    float a0 = 0.f, a1 = 0.f, a2 = 0.f, a3 = 0.f;
    for (int i = lane; i < DIM; i += 32) {
        float  hv = hr[i];
        float4 w  = reinterpret_cast<const float4*>(wg)[i];
        a0 += hv * w.x; a1 += hv * w.y; a2 += hv * w.z; a3 += hv * w.w;
    }
    #pragma unroll
    for (int o = 16; o; o >>= 1) {
        a0 += __shfl_xor_sync(0xffffffffu, a0, o);
        a1 += __shfl_xor_sync(0xffffffffu, a1, o);
        a2 += __shfl_xor_sync(0xffffffffu, a2, o);
        a3 += __shfl_xor_sync(0xffffffffu, a3, o);
    }
    if (lane == 0) {
        float l[4] = {a0, a1, a2, a3};
        int i0 = 0;
        #pragma unroll
        for (int e = 1; e < 4; e++) if (l[e] > l[i0]) i0 = e;
        int i1 = -1;
        #pragma unroll
        for (int e = 0; e < 4; e++)
            if (e != i0 && (i1 < 0 || l[e] > l[i1])) i1 = e;
        float p1  = expf(l[i1] - l[i0]);
        float inv = 1.0f / (1.0f + p1);
        int p = atomicAdd(&g_cnt[i0], 1);
        g_tok[i0 * NT + p] = gw;
        g_slot[gw * 2]     = i0 * NT + p;
        g_gval[gw * 2]     = inv;
        int q = atomicAdd(&g_cnt[i1], 1);
        g_tok[i1 * NT + q] = gw;
        g_slot[gw * 2 + 1] = i1 * NT + q;
        g_gval[gw * 2 + 1] = p1 * inv;
    }
}

// ---------------- wmma tf32 grouped GEMM: small CTAs, R12-proven phase structure ----------------
// D[64,64] = A[64,K] @ B[K,64]; 4 warps, warp w -> rows [16w,16w+16) x all 64 cols.
// Inline tf32 rounding at smem-store. Single-stage smem, load -> sync -> mma -> sync.
template<int KTOT, int NTOT, bool GATHER, bool ROUND_OUT>
__global__ void __launch_bounds__(128) gemm_kernel(const float* __restrict__ Ain,
                                                   const float* __restrict__ Bg,
                                                   const float* __restrict__ bias) {
    const int e   = blockIdx.z;
    const int cnt = g_cnt[e];
    const int m0  = blockIdx.y * BM;
    if (m0 >= cnt) return;
    const int n0  = blockIdx.x * BN;

    const float* Ag = GATHER ? Ain : g_mid;
    float* outp     = ROUND_OUT ? g_mid : g_y;

    __shared__ float As[BM][APITCH];   // 9.0 KB
    __shared__ float Bs[BK][BPITCH];   // 8.5 KB
    __shared__ float Epi[4][256];      // 4.0 KB   (21.5 KB total)

    const int tid  = threadIdx.x;
    const int wid  = tid >> 5;
    const int lane = tid & 31;

    // A loader: row lr = tid>>1 (0..63), 16 k's at lk (4 x float4)
    const int lr = tid >> 1, lk = (tid & 1) * 16;
    int arow = m0 + lr; if (arow >= cnt) arow = cnt - 1;
    const float* aptr;
    if (GATHER) aptr = Ag + (size_t)g_tok[e * NT + arow] * KTOT + lk;
    else        aptr = Ag + ((size_t)e * NT + arow) * KTOT + lk;

    // B loader: k-row kb = tid>>2 (0..31), 16 cols at bc (4 x float4)
    const int kb = tid >> 2, bc = (tid & 3) * 16;
    const float* bptr = Bg + (size_t)e * KTOT * NTOT + (size_t)kb * NTOT + n0 + bc;

    wmma::fragment<wmma::accumulator, 16, 16, 8, float> acc[4];
    #pragma unroll
    for (int j = 0; j < 4; j++) wmma::fill_fragment(acc[j], 0.0f);

    const int KT = KTOT / BK;

    for (int kt = 0; kt < KT; kt++) {
        // ---- load + round tile kt into smem (R12-proven phase) ----
        {
            const float* ap = aptr + kt * BK;
            #pragma unroll
            for (int c = 0; c < 4; c++) {
                float4 v = *reinterpret_cast<const float4*>(ap + c * 4);
                As[lr][lk + c * 4 + 0] = wmma::__float_to_tf32(v.x);
                As[lr][lk + c * 4 + 1] = wmma::__float_to_tf32(v.y);
                As[lr][lk + c * 4 + 2] = wmma::__float_to_tf32(v.z);
                As[lr][lk + c * 4 + 3] = wmma::__float_to_tf32(v.w);
            }
            const float* bp = bptr + (size_t)kt * BK * NTOT;
            #pragma unroll
            for (int c = 0; c < 4; c++) {
                float4 v = *reinterpret_cast<const float4*>(bp + c * 4);
                Bs[kb][bc + c * 4 + 0] = wmma::__float_to_tf32(v.x);
                Bs[kb][bc + c * 4 + 1] = wmma::__float_to_tf32(v.y);
                Bs[kb][bc + c * 4 + 2] = wmma::__float_to_tf32(v.z);
                Bs[kb][bc + c * 4 + 3] = wmma::__float_to_tf32(v.w);
            }
        }
        __syncthreads();

        // ---- compute: 4 k8 steps ----
        #pragma unroll
        for (int ks = 0; ks < 4; ks++) {
            wmma::fragment<wmma::matrix_a, 16, 16, 8, wmma::precision::tf32, wmma::row_major> af;
            wmma::load_matrix_sync(af, &As[wid * 16][ks * 8], APITCH);
            wmma::fragment<wmma::matrix_b, 16, 16, 8, wmma::precision::tf32, wmma::row_major> bf;
            #pragma unroll
            for (int j = 0; j < 4; j++) {
                wmma::load_matrix_sync(bf, &Bs[ks * 8][16 * j], BPITCH);
                wmma::mma_sync(acc[j], af, bf, acc[j]);
            }
        }
        __syncthreads();
    }

    // ---- epilogue (proven staging): bias (+relu+round), float4 stores ----
    float* epi = &Epi[wid][0];
    const int rr = lane >> 1;
    const int cc = (lane & 1) * 8;
    #pragma unroll
    for (int j = 0; j < 4; j++) {
        wmma::store_matrix_sync(epi, acc[j], 16, wmma::mem_row_major);
        __syncwarp();
        const int r     = m0 + wid * 16 + rr;
        const int cbase = n0 + 16 * j + cc;
        if (r < cnt) {
            float v[8];
            #pragma unroll
            for (int t = 0; t < 8; t++) {
                v[t] = epi[rr * 16 + cc + t] + bias[(size_t)e * NTOT + cbase + t];
                if (ROUND_OUT) v[t] = wmma::__float_to_tf32(fmaxf(v[t], 0.f));
            }
            float* orow = outp + ((size_t)e * NT + r) * NTOT + cbase;
            *reinterpret_cast<float4*>(orow)     = make_float4(v[0], v[1], v[2], v[3]);
            *reinterpret_cast<float4*>(orow + 4) = make_float4(v[4], v[5], v[6], v[7]);
        }
        __syncwarp();
    }
}

// ---------------- combine (proven) ----------------
__global__ void combine_kernel(float* __restrict__ out) {
    int idx = blockIdx.x * blockDim.x + threadIdx.x;
    if (idx >= NT * (DIM / 4)) return;
    int n = idx / (DIM / 4);
    int c = idx % (DIM / 4);
    int   sA = g_slot[n * 2],     sB = g_slot[n * 2 + 1];
    float gA = g_gval[n * 2],     gB = g_gval[n * 2 + 1];
    const float4* y4 = reinterpret_cast<const float4*>(g_y);
    float4 a = y4[(size_t)sA * (DIM / 4) + c];
    float4 b = y4[(size_t)sB * (DIM / 4) + c];
    float4 o;
    o.x = gA * a.x + gB * b.x;
    o.y = gA * a.y + gB * b.y;
    o.z = gA * a.z + gB * b.z;
    o.w = gA * a.w + gB * b.w;
    reinterpret_cast<float4*>(out)[idx] = o;
}

// ---------------- launch ----------------
extern "C" void kernel_launch(void* const* d_in, const int* in_sizes, int n_in,
                              void* d_out, int out_size) {
    const float* h  = (const float*)d_in[0];   // [NT, DIM]
    const float* wg = (const float*)d_in[1];   // [DIM, NE]
    const float* w1 = (const float*)d_in[2];   // [NE, DIM, HID] = [e][k][n]
    const float* b1 = (const float*)d_in[3];   // [NE, HID]
    const float* w2 = (const float*)d_in[4];   // [NE, HID, DIM] = [e][k][n]
    const float* b2 = (const float*)d_in[5];   // [NE, DIM]
    float* out = (float*)d_out;                // [NT, DIM]

    reset_kernel<<<1, 32>>>();
    gate_kernel<<<(NT * 32) / 256, 256>>>(h, wg);
    {   // GEMM1: mid = round_tf32(relu(h[tok] @ w1[e] + b1))
        dim3 g(HID / BN, NT / BM, NE);
        gemm_kernel<DIM, HID, true, true><<<g, 128>>>(h, w1, b1);
    }
    {   // GEMM2: y = mid @ w2[e] + b2
        dim3 g(DIM / BN, NT / BM, NE);
        gemm_kernel<HID, DIM, false, false><<<g, 128>>>(h /*unused*/, w2, b2);
    }
    combine_kernel<<<(NT * (DIM / 4) + 255) / 256, 256>>>(out);
}